// round 12
// baseline (speedup 1.0000x reference)
#include <cuda_runtime.h>
#include <cstddef>

#define NN 2048
#define FF 32
#define EE 16
#define KK 32
#define NZCAP 128        // per-warp nonzero list capacity (256 cols @ p=0.05)
#define NCOPY 512        // copy blocks (1/5 of grid)
#define GRID  (2048 + NCOPY)

// ---------------------------------------------------------------------------
// Single fused kernel, heterogeneous roles by blockIdx:
//   bid%5==4  -> copy block: depth-8 register-staged stream of 1/NCOPY of edges
//   otherwise -> compute block for row i:
//       adj scan+copy -> per-warp nonzero list,
//       pipelined gather: on-the-fly node_part (nodes L2-hot) + edge matvec,
//       epilogue: node_term on the fly, (1+eps)*nt + msg, @W_net, relu.
// ---------------------------------------------------------------------------
__global__ __launch_bounds__(256, 4) void gin_hetero(
        const float* __restrict__ adj,
        const float* __restrict__ nodes,
        const float* __restrict__ edges,
        const float* __restrict__ W_ne,   // [F+E, F]
        const float* __restrict__ b_ne,
        const float* __restrict__ W_n,
        const float* __restrict__ b_n,
        const float* __restrict__ W_net,
        const float* __restrict__ b_net,
        const float* __restrict__ eps_p,
        float* __restrict__ out_adj,
        float* __restrict__ out_net,
        float* __restrict__ out_edges) {
    const int bid = blockIdx.x;
    const int tid = threadIdx.x;

    // ======================= COPY ROLE =======================
    if ((bid % 5) == 4) {
        const int chunk = bid / 5;                       // 0..NCOPY-1
        constexpr size_t NV = (size_t)NN * NN * EE / 4;  // 16,777,216 float4
        constexpr size_t CV = NV / NCOPY;                // 32768 float4 / chunk
        const float4* __restrict__ src = (const float4*)edges + (size_t)chunk * CV;
        float4* __restrict__ dst = (float4*)out_edges + (size_t)chunk * CV;
        // 32768/256 = 128 per thread = 16 batches of depth 8
#pragma unroll 1
        for (int b = 0; b < 16; b++) {
            float4 r[8];
            const size_t base = (size_t)b * 8 * 256 + tid;
#pragma unroll
            for (int u = 0; u < 8; u++) r[u] = src[base + (size_t)u * 256];
#pragma unroll
            for (int u = 0; u < 8; u++) __stcs(&dst[base + (size_t)u * 256], r[u]);
        }
        return;
    }

    // ====================== COMPUTE ROLE =====================
    const int i    = (bid / 5) * 4 + (bid % 5);          // row 0..2047
    const int lane = tid & 31;
    const int warp = tid >> 5;                           // 0..7

    __shared__ float sWnf[FF * FF];       // node half of W_ne
    __shared__ float sWE [EE * FF];       // edge half of W_ne
    __shared__ float sWn [FF * FF];
    __shared__ float sWnet[FF * KK];
    __shared__ float smsg[8][FF];
    __shared__ float smid[FF];
    __shared__ int   sjix[8][NZCAP];
    __shared__ float sja [8][NZCAP];

    for (int t = tid; t < FF * FF; t += 256) { sWnf[t] = W_ne[t]; sWn[t] = W_n[t]; }
    for (int t = tid; t < EE * FF; t += 256) sWE[t]   = W_ne[FF * FF + t];
    for (int t = tid; t < FF * KK; t += 256) sWnet[t] = W_net[t];
    __syncthreads();

    const size_t rowbase = (size_t)i * NN;
    const float* adj_row = adj + rowbase;
    float* oadj_row = out_adj + rowbase;

    // ---- adj scan + fused adj copy; build per-warp nonzero list ----
    int cnt = 0;
#pragma unroll
    for (int c = 0; c < 8; c++) {
        const int j = c * 256 + warp * 32 + lane;
        const float a = adj_row[j];
        oadj_row[j] = a;
        const unsigned m = __ballot_sync(0xffffffffu, a != 0.f);
        if (a != 0.f) {
            const int pos = cnt + __popc(m & ((1u << lane) - 1u));
            if (pos < NZCAP) { sjix[warp][pos] = j; sja[warp][pos] = a; }
        }
        cnt += __popc(m);
    }
    if (cnt > NZCAP) cnt = NZCAP;
    __syncwarp();

    // ---- pipelined sparse message accumulation (node_part on the fly) ----
    const float bne = b_ne[lane];
    float msg = 0.f;

    int   jcur = 0;
    float evcur = 0.f, nvcur = 0.f, acur = 0.f;
    if (cnt > 0) {
        jcur  = sjix[warp][0];
        acur  = sja[warp][0];
        evcur = (lane < EE) ? edges[(rowbase + (size_t)jcur) * EE + lane] : 0.f;
        nvcur = nodes[jcur * FF + lane];               // L2-hot (256 KB)
    }
    for (int t = 0; t < cnt; t++) {
        int   jnxt = 0;
        float evnxt = 0.f, nvnxt = 0.f, anxt = 0.f;
        if (t + 1 < cnt) {                             // prefetch next
            jnxt  = sjix[warp][t + 1];
            anxt  = sja[warp][t + 1];
            evnxt = (lane < EE) ? edges[(rowbase + (size_t)jnxt) * EE + lane] : 0.f;
            nvnxt = nodes[jnxt * FF + lane];
        }
        float acc = bne;
#pragma unroll
        for (int k = 0; k < FF; k++)
            acc = fmaf(__shfl_sync(0xffffffffu, nvcur, k),
                       sWnf[k * FF + lane], acc);
#pragma unroll
        for (int e = 0; e < EE; e++)
            acc = fmaf(__shfl_sync(0xffffffffu, evcur, e),
                       sWE[e * FF + lane], acc);
        msg = fmaf(acur, fmaxf(acc, 0.f), msg);
        jcur = jnxt; evcur = evnxt; nvcur = nvnxt; acur = anxt;
    }

    smsg[warp][lane] = msg;
    __syncthreads();

    // ---- epilogue: node_term on the fly, then W_net matvec ----
    if (warp == 0) {
        float mtot = 0.f;
#pragma unroll
        for (int w = 0; w < 8; w++) mtot += smsg[w][lane];

        const float nv = nodes[i * FF + lane];
        float acct = b_n[lane];
#pragma unroll
        for (int k = 0; k < FF; k++)
            acct = fmaf(__shfl_sync(0xffffffffu, nv, k),
                        sWn[k * FF + lane], acct);
        const float nterm = fmaxf(acct, 0.f);

        const float eps = eps_p[0];
        const float mid = (1.f + eps) * nterm + mtot;
        smid[lane] = mid;
        __syncwarp();

        float acc = b_net[lane];
#pragma unroll
        for (int f = 0; f < FF; f++)
            acc = fmaf(smid[f], sWnet[f * KK + lane], acc);
        out_net[i * KK + lane] = fmaxf(acc, 0.f);
    }
}

// ---------------------------------------------------------------------------
// kernel_launch — inputs per metadata order:
// adj, nodes_features, edges_features, W_ne, b_ne, W_n, b_n, W_net, b_net, eps
// Output tuple flattened: [adj (N*N), out (N*K), edges_features (N*N*E)]
// ---------------------------------------------------------------------------
extern "C" void kernel_launch(void* const* d_in, const int* in_sizes, int n_in,
                              void* d_out, int out_size) {
    const float* adj    = (const float*)d_in[0];
    const float* nodes  = (const float*)d_in[1];
    const float* edges  = (const float*)d_in[2];
    const float* W_ne   = (const float*)d_in[3];
    const float* b_ne   = (const float*)d_in[4];
    const float* W_n    = (const float*)d_in[5];
    const float* b_n    = (const float*)d_in[6];
    const float* W_net  = (const float*)d_in[7];
    const float* b_net  = (const float*)d_in[8];
    const float* eps    = (const float*)d_in[9];

    float* out       = (float*)d_out;
    float* out_adj   = out;
    float* out_net   = out + (size_t)NN * NN;
    float* out_edges = out + (size_t)NN * NN + (size_t)NN * KK;

    gin_hetero<<<GRID, 256>>>(adj, nodes, edges, W_ne, b_ne, W_n, b_n,
                              W_net, b_net, eps, out_adj, out_net, out_edges);
}

// round 14
// speedup vs baseline: 1.1723x; 1.1723x over previous
#include <cuda_runtime.h>
#include <cstddef>

#define NN 2048
#define FF 32
#define EE 16
#define KK 32
#define NZCAP 128        // per-warp nonzero list capacity (256 cols @ p=0.05)
#define NCOPY 1024       // copy blocks (1/3 of grid)
#define GRID  (2048 + NCOPY)

// Scratch (allocation-free rule: __device__ globals)
__device__ float g_node_part[NN * FF];  // nodes @ W_ne[:F]
__device__ float g_node_term[NN * FF];  // relu(nodes @ W_n + b_n)

// ---------------------------------------------------------------------------
// Kernel 1: per-node precompute. 8 rows per 256-thread block. (~2 us)
// ---------------------------------------------------------------------------
__global__ void gin_precompute(const float* __restrict__ nodes,
                               const float* __restrict__ W_ne,
                               const float* __restrict__ W_n,
                               const float* __restrict__ b_n) {
    __shared__ float sWne[FF * FF];
    __shared__ float sWn[FF * FF];
    const int tid = threadIdx.x;
    for (int t = tid; t < FF * FF; t += 256) {
        sWne[t] = W_ne[t];   // first F rows of W_ne
        sWn[t]  = W_n[t];
    }
    __syncthreads();

    const int f   = tid & 31;
    const int r   = tid >> 5;
    const int row = blockIdx.x * 8 + r;
    if (row >= NN) return;

    float accp = 0.f;
    float acct = b_n[f];
    const float* nrow = nodes + row * FF;
#pragma unroll
    for (int k = 0; k < FF; k++) {
        const float x = nrow[k];
        accp = fmaf(x, sWne[k * FF + f], accp);
        acct = fmaf(x, sWn[k * FF + f],  acct);
    }
    g_node_part[row * FF + f] = accp;
    g_node_term[row * FF + f] = fmaxf(acct, 0.f);
}

// ---------------------------------------------------------------------------
// Kernel 2: heterogeneous-role grid (ratio 2 compute : 1 copy).
//   bid%3==2  -> copy block: stream 1/NCOPY of edges (contiguous 256 KB chunk)
//   otherwise -> compute block for row i: adj scan+copy, nonzero list,
//                pipelined sparse message, epilogue.
// ---------------------------------------------------------------------------
__global__ __launch_bounds__(256) void gin_hetero(
        const float* __restrict__ adj,
        const float* __restrict__ edges,
        const float* __restrict__ W_ne,   // rows F..F+E used
        const float* __restrict__ b_ne,
        const float* __restrict__ W_net,
        const float* __restrict__ b_net,
        const float* __restrict__ eps_p,
        float* __restrict__ out_adj,
        float* __restrict__ out_net,
        float* __restrict__ out_edges) {
    const int bid = blockIdx.x;
    const int tid = threadIdx.x;

    // ======================= COPY ROLE =======================
    if ((bid % 3) == 2) {
        const int chunk = bid / 3;                       // 0..NCOPY-1
        constexpr size_t NV = (size_t)NN * NN * EE / 4;  // 16,777,216 float4
        constexpr size_t CV = NV / NCOPY;                // 16384 float4 / chunk
        const float4* __restrict__ src = (const float4*)edges + (size_t)chunk * CV;
        float4* __restrict__ dst = (float4*)out_edges + (size_t)chunk * CV;
#pragma unroll 8
        for (size_t t = tid; t < CV; t += 256)
            dst[t] = src[t];
        return;
    }

    // ====================== COMPUTE ROLE =====================
    const int i    = (bid / 3) * 2 + (bid % 3);          // row 0..2047
    const int lane = tid & 31;
    const int warp = tid >> 5;                           // 0..7

    __shared__ float sWE[EE * FF];
    __shared__ float sWnet[FF * KK];
    __shared__ float smsg[8][FF];
    __shared__ float smid[FF];
    __shared__ int   sjix[8][NZCAP];
    __shared__ float sja [8][NZCAP];

    for (int t = tid; t < EE * FF; t += 256) sWE[t]   = W_ne[FF * FF + t];
    for (int t = tid; t < FF * KK; t += 256) sWnet[t] = W_net[t];
    __syncthreads();

    const size_t rowbase = (size_t)i * NN;
    const float* adj_row = adj + rowbase;
    float* oadj_row = out_adj + rowbase;

    // ---- adj scan + fused adj copy; build per-warp nonzero list ----
    int cnt = 0;
#pragma unroll
    for (int c = 0; c < 8; c++) {
        const int j = c * 256 + warp * 32 + lane;
        const float a = adj_row[j];
        oadj_row[j] = a;
        const unsigned m = __ballot_sync(0xffffffffu, a != 0.f);
        if (a != 0.f) {
            const int pos = cnt + __popc(m & ((1u << lane) - 1u));
            if (pos < NZCAP) { sjix[warp][pos] = j; sja[warp][pos] = a; }
        }
        cnt += __popc(m);
    }
    if (cnt > NZCAP) cnt = NZCAP;
    __syncwarp();

    // ---- pipelined sparse message accumulation ----
    const float bne = b_ne[lane];
    float msg = 0.f;

    int   jcur = 0;
    float evcur = 0.f, npcur = 0.f, acur = 0.f;
    if (cnt > 0) {
        jcur  = sjix[warp][0];
        acur  = sja[warp][0];
        evcur = (lane < EE) ? edges[(rowbase + (size_t)jcur) * EE + lane] : 0.f;
        npcur = g_node_part[jcur * FF + lane];
    }
    for (int t = 0; t < cnt; t++) {
        int   jnxt = 0;
        float evnxt = 0.f, npnxt = 0.f, anxt = 0.f;
        if (t + 1 < cnt) {                               // prefetch next
            jnxt  = sjix[warp][t + 1];
            anxt  = sja[warp][t + 1];
            evnxt = (lane < EE) ? edges[(rowbase + (size_t)jnxt) * EE + lane] : 0.f;
            npnxt = g_node_part[jnxt * FF + lane];
        }
        float acc = 0.f;
#pragma unroll
        for (int e = 0; e < EE; e++)
            acc = fmaf(__shfl_sync(0xffffffffu, evcur, e),
                       sWE[e * FF + lane], acc);
        const float v = npcur + acc + bne;
        msg = fmaf(acur, fmaxf(v, 0.f), msg);
        jcur = jnxt; evcur = evnxt; npcur = npnxt; acur = anxt;
    }

    smsg[warp][lane] = msg;
    __syncthreads();

    // ---- epilogue ----
    if (warp == 0) {
        float mtot = 0.f;
#pragma unroll
        for (int w = 0; w < 8; w++) mtot += smsg[w][lane];
        const float eps = eps_p[0];
        const float mid = (1.f + eps) * g_node_term[i * FF + lane] + mtot;
        smid[lane] = mid;
        __syncwarp();
        float acc = b_net[lane];
#pragma unroll
        for (int f = 0; f < FF; f++)
            acc = fmaf(smid[f], sWnet[f * KK + lane], acc);
        out_net[i * KK + lane] = fmaxf(acc, 0.f);
    }
}

// ---------------------------------------------------------------------------
// kernel_launch — inputs per metadata order:
// adj, nodes_features, edges_features, W_ne, b_ne, W_n, b_n, W_net, b_net, eps
// Output tuple flattened: [adj (N*N), out (N*K), edges_features (N*N*E)]
// ---------------------------------------------------------------------------
extern "C" void kernel_launch(void* const* d_in, const int* in_sizes, int n_in,
                              void* d_out, int out_size) {
    const float* adj    = (const float*)d_in[0];
    const float* nodes  = (const float*)d_in[1];
    const float* edges  = (const float*)d_in[2];
    const float* W_ne   = (const float*)d_in[3];
    const float* b_ne   = (const float*)d_in[4];
    const float* W_n    = (const float*)d_in[5];
    const float* b_n    = (const float*)d_in[6];
    const float* W_net  = (const float*)d_in[7];
    const float* b_net  = (const float*)d_in[8];
    const float* eps    = (const float*)d_in[9];

    float* out       = (float*)d_out;
    float* out_adj   = out;
    float* out_net   = out + (size_t)NN * NN;
    float* out_edges = out + (size_t)NN * NN + (size_t)NN * KK;

    gin_precompute<<<NN / 8, 256>>>(nodes, W_ne, W_n, b_n);
    gin_hetero<<<GRID, 256>>>(adj, edges, W_ne, b_ne, W_net, b_net, eps,
                              out_adj, out_net, out_edges);
}